// round 13
// baseline (speedup 1.0000x reference)
#include <cuda_runtime.h>
#include <cuda_bf16.h>
#include <math.h>
#include <float.h>
#include <stdint.h>

#define S   512
#define Bn  256
#define DIN 202
#define Hh  100
#define Tt  19
#define SB  (S*Bn)

// ---------------- scratch (device globals; no runtime allocation) ----------
__device__ float g_xp[SB * 200];     // input projections (biases included)
__device__ float g_h [SB * 200];     // concatenated hidden states
__device__ float g_probs[SB * Tt];   // softmax emissions
__device__ float g_nd[S];            // per-sequence (num - den)

// packed fp32x2 FMA (Blackwell FFMA2; PTX >= sm_100, family-generic)
__device__ __forceinline__ void fma2(unsigned long long& d,
                                     unsigned long long a, unsigned long long b) {
    asm("fma.rn.f32x2 %0, %1, %2, %0;" : "+l"(d) : "l"(a), "l"(b));
}
__device__ __forceinline__ unsigned long long pack2(float lo, float hi) {
    unsigned long long r;
    asm("mov.b64 %0, {%1, %2};" : "=l"(r) : "f"(lo), "f"(hi));
    return r;
}
__device__ __forceinline__ void unpack2(unsigned long long v, float& lo, float& hi) {
    asm("mov.b64 {%0, %1}, %2;" : "=f"(lo), "=f"(hi) : "l"(v));
}

// ============================================================================
// Stage 1: persistent bf16 GEMM via mma.sync.m16n8k16.
// D[131072, 200] = x[131072, 202] @ W[200, 202]^T, K padded to 208 (13x16),
// N tiled as 25 x 8. W in smem once; full 128x208 A tile per iteration ->
// ONE barrier pair per tile. Fill loops use power-of-2 index decomposition
// (r = idx>>7, j = idx&127) — R9's /104 %104 div chains were the regression.
// Stride 108 words: fragment bank map (12g + tig) mod 32 covers all banks.
// ============================================================================
#define KCHUNKS 13
#define NTILES  25
#define MTILES  (SB / 128)            // 1024
#define RSTRIDE 108                   // words (uint32) per row, A and B
#define SM_B    1024
#define B_BYTES (200 * RSTRIDE * 4)   // 86400
#define SM_A    (SM_B + B_BYTES)      // 87424
#define A_BYTES (128 * RSTRIDE * 4)   // 55296
#define PROJ_SMEM (SM_A + A_BYTES)    // 142720

__global__ __launch_bounds__(256, 1) void proj_mma(
    const float* __restrict__ x,
    const float* __restrict__ Wf, const float* __restrict__ Wb,
    const float* __restrict__ bif, const float* __restrict__ bhf,
    const float* __restrict__ bib, const float* __restrict__ bhb)
{
    extern __shared__ __align__(16) char smem[];
    float*    bias_s = (float*)smem;
    uint32_t* Bw     = (uint32_t*)(smem + SM_B);
    uint32_t* Aw     = (uint32_t*)(smem + SM_A);

    const int tid = threadIdx.x;
    const int w   = tid >> 5, lane = tid & 31;
    const int g   = lane >> 2, tig = lane & 3;

    if (tid < 100) {
        bias_s[tid]       = bif[tid] + bhf[tid];
        bias_s[100 + tid] = bib[tid] + bhb[tid];
    }

    // ---- W -> smem bf16 once (k-pad words written zero; no divisions) ----
    for (int idx = tid; idx < 200 * 128; idx += 256) {
        const int n = idx >> 7, j = idx & 127;
        if (j < 104) {
            uint32_t v = 0;
            if (j < 101) {
                const float2 f = ((const float2*)((n < 100) ? (Wf + (size_t)n * DIN)
                                                            : (Wb + (size_t)(n - 100) * DIN)))[j];
                __nv_bfloat162 h2 = __floats2bfloat162_rn(f.x, f.y);
                v = *(uint32_t*)&h2;
            }
            Bw[n * RSTRIDE + j] = v;
        }
    }
    __syncthreads();

    for (int tile = blockIdx.x; tile < MTILES; tile += gridDim.x) {
        // ---- A tile fill (coalesced, division-free, pads zeroed) ----
        const float* xt = x + (size_t)tile * 128 * DIN;
        #pragma unroll 4
        for (int idx = tid; idx < 128 * 128; idx += 256) {
            const int r = idx >> 7, j = idx & 127;
            if (j < 104) {
                uint32_t v = 0;
                if (j < 101) {
                    const float2 f = ((const float2*)(xt + (size_t)r * DIN))[j];
                    __nv_bfloat162 h2 = __floats2bfloat162_rn(f.x, f.y);
                    v = *(uint32_t*)&h2;
                }
                Aw[r * RSTRIDE + j] = v;
            }
        }
        __syncthreads();

        float c[NTILES][4];
        #pragma unroll
        for (int j = 0; j < NTILES; j++)
            #pragma unroll
            for (int q = 0; q < 4; q++) c[j][q] = 0.f;

        const int r0 = w * 16 + g, r1 = r0 + 8;
        #pragma unroll 1
        for (int kc = 0; kc < KCHUNKS; kc++) {
            const int kw = kc * 8 + tig;
            const uint32_t a0 = Aw[r0 * RSTRIDE + kw];
            const uint32_t a1 = Aw[r1 * RSTRIDE + kw];
            const uint32_t a2 = Aw[r0 * RSTRIDE + kw + 4];
            const uint32_t a3 = Aw[r1 * RSTRIDE + kw + 4];
            #pragma unroll
            for (int j = 0; j < NTILES; j++) {
                const uint32_t* bp = Bw + (8 * j + g) * RSTRIDE + kw;
                const uint32_t b0 = bp[0];
                const uint32_t b1 = bp[4];
                asm volatile(
                    "mma.sync.aligned.m16n8k16.row.col.f32.bf16.bf16.f32 "
                    "{%0,%1,%2,%3}, {%4,%5,%6,%7}, {%8,%9}, {%0,%1,%2,%3};"
                    : "+f"(c[j][0]), "+f"(c[j][1]), "+f"(c[j][2]), "+f"(c[j][3])
                    : "r"(a0), "r"(a1), "r"(a2), "r"(a3), "r"(b0), "r"(b1));
            }
        }

        // epilogue: thread holds rows g/g+8 of its warp strip, cols 8j+2tig..+1
        const int m0 = tile * 128 + w * 16;
        #pragma unroll
        for (int j = 0; j < NTILES; j++) {
            const int col = 8 * j + tig * 2;
            const float bx = bias_s[col], by = bias_s[col + 1];
            *(float2*)&g_xp[(size_t)(m0 + g)     * 200 + col] =
                make_float2(c[j][0] + bx, c[j][1] + by);
            *(float2*)&g_xp[(size_t)(m0 + g + 8) * 200 + col] =
                make_float2(c[j][2] + bx, c[j][3] + by);
        }
        __syncthreads();   // MMA reads done before next tile's A fill
    }
}

// ============================================================================
// Stage 2: recurrent tanh scan. 512 blocks (dir,b). Whh row packed f32x2 in
// registers (50 FFMA2 per dot), 4-deep xp prefetch ring, 4 packed accumulator
// chains, fast tanh. Full fp32 precision.
// ============================================================================
__global__ __launch_bounds__(128) void rnn_scan(
    const float* __restrict__ Whf, const float* __restrict__ Whb)
{
    const int dir = (blockIdx.x >= Bn) ? 1 : 0;
    const int b   = dir ? (blockIdx.x - Bn) : blockIdx.x;
    const int tid = threadIdx.x;
    const float* Whh = dir ? Whb : Whf;
    const bool act = tid < 100;

    __shared__ __align__(16) float hs[2][100];

    unsigned long long w2[50];
    if (act) {
        #pragma unroll
        for (int j = 0; j < 50; j++)
            w2[j] = pack2(Whh[tid * 100 + 2 * j], Whh[tid * 100 + 2 * j + 1]);
        hs[0][tid] = 0.f;
    }

    const size_t base = (size_t)b * 200 + (size_t)dir * 100 + tid;
    float pf[4];
    #pragma unroll
    for (int i = 0; i < 4; i++) {
        int t = dir ? (S - 1 - i) : i;
        pf[i] = act ? g_xp[(size_t)t * (Bn * 200) + base] : 0.f;
    }
    __syncthreads();

    int p = 0;
    for (int step = 0; step < S; step++) {
        const int t = dir ? (S - 1 - step) : step;
        float acc = pf[step & 3];
        if (step + 4 < S && act) {
            int t4 = dir ? (S - 1 - (step + 4)) : (step + 4);
            pf[step & 3] = g_xp[(size_t)t4 * (Bn * 200) + base];
        }
        if (act) {
            unsigned long long a0 = pack2(acc, 0.f), a1 = 0ull, a2 = 0ull, a3 = 0ull;
            #pragma unroll
            for (int jj = 0; jj < 25; jj++) {
                ulonglong2 hh = *(const ulonglong2*)&hs[p][jj * 4];
                if (jj & 1) { fma2(a2, hh.x, w2[2 * jj]); fma2(a3, hh.y, w2[2 * jj + 1]); }
                else        { fma2(a0, hh.x, w2[2 * jj]); fma2(a1, hh.y, w2[2 * jj + 1]); }
            }
            float f0, f1, f2, f3, f4, f5, f6, f7;
            unpack2(a0, f0, f1); unpack2(a1, f2, f3);
            unpack2(a2, f4, f5); unpack2(a3, f6, f7);
            float s = ((f0 + f1) + (f2 + f3)) + ((f4 + f5) + (f6 + f7));
            float e = __expf(2.f * s);                    // tanh = 1 - 2/(e^{2s}+1)
            float nh = 1.f - __fdividef(2.f, e + 1.f);
            hs[p ^ 1][tid] = nh;
            g_h[(size_t)t * (Bn * 200) + base] = nh;
        }
        __syncthreads();
        p ^= 1;
    }
}

// ============================================================================
// Stage 3: logits = h @ W_tag^T + b_tag, softmax over T=19. Warp per row.
// Packed f32x2 dot: Wt2[k2][t] = (W[2k2][t], W[2k2+1][t]) pre-paired in smem;
// 50 FFMA2 per row instead of 200 FFMA. Exact fp32 math.
// ============================================================================
__global__ __launch_bounds__(256) void tag_softmax(
    const float* __restrict__ Wtag, const float* __restrict__ btag)
{
    __shared__ __align__(16) float hrow[8][200];
    __shared__ __align__(16) unsigned long long Wt2[100 * Tt];  // [k-pair][t]
    __shared__ float bt[Tt];
    const int tid = threadIdx.x;

    // build pair table (power-of-2 index decomposition, no divisions)
    for (int idx = tid; idx < 100 * 32; idx += 256) {
        const int k2 = idx >> 5, t = idx & 31;
        if (t < Tt)
            Wt2[k2 * Tt + t] = pack2(Wtag[t * 200 + 2 * k2],
                                     Wtag[t * 200 + 2 * k2 + 1]);
    }
    if (tid < Tt) bt[tid] = btag[tid];
    __syncthreads();

    const int warp = tid >> 5, lane = tid & 31;
    const unsigned FULL = 0xffffffffu;
    for (int row = blockIdx.x * 8 + warp; row < SB; row += gridDim.x * 8) {
        const float4* hr4 = (const float4*)(g_h + (size_t)row * 200);
        float4* dst4 = (float4*)hrow[warp];
        for (int i = lane; i < 50; i += 32) dst4[i] = hr4[i];
        __syncwarp();
        float acc = 0.f;
        if (lane < Tt) {
            const unsigned long long* h2 = (const unsigned long long*)hrow[warp];
            unsigned long long a0 = 0ull, a1 = 0ull, a2 = 0ull, a3 = 0ull;
            #pragma unroll
            for (int k2 = 0; k2 < 100; k2 += 4) {
                fma2(a0, h2[k2 + 0], Wt2[(k2 + 0) * Tt + lane]);
                fma2(a1, h2[k2 + 1], Wt2[(k2 + 1) * Tt + lane]);
                fma2(a2, h2[k2 + 2], Wt2[(k2 + 2) * Tt + lane]);
                fma2(a3, h2[k2 + 3], Wt2[(k2 + 3) * Tt + lane]);
            }
            float f0, f1, f2, f3, f4, f5, f6, f7;
            unpack2(a0, f0, f1); unpack2(a1, f2, f3);
            unpack2(a2, f4, f5); unpack2(a3, f6, f7);
            acc = bt[lane] + (((f0 + f1) + (f2 + f3)) + ((f4 + f5) + (f6 + f7)));
        }
        float v = (lane < Tt) ? acc : -FLT_MAX;
        float m = v;
        #pragma unroll
        for (int o = 16; o; o >>= 1) m = fmaxf(m, __shfl_xor_sync(FULL, m, o));
        float e = (lane < Tt) ? __expf(acc - m) : 0.f;
        float ssum = e;
        #pragma unroll
        for (int o = 16; o; o >>= 1) ssum += __shfl_xor_sync(FULL, ssum, o);
        if (lane < Tt) g_probs[(size_t)row * Tt + lane] = e / ssum;
        __syncwarp();
    }
}

// ============================================================================
// Stage 4: fused CRF numerator + forward (R8 version, measured 49.6us).
// Warp per sequence n; lane-0 alpha broadcast as LSE shift; emission prefetch.
// ============================================================================
__device__ __forceinline__ int clamp_tag(int t) {
    return t < 0 ? 0 : (t >= Tt ? Tt - 1 : t);
}

__global__ __launch_bounds__(128) void crf_kernel(
    const int* __restrict__ y, const float* __restrict__ trans,
    const float* __restrict__ start_t, const float* __restrict__ end_t)
{
    __shared__ __align__(16) float pbuf[4][32];
    const int tid = threadIdx.x, warp = tid >> 5, lane = tid & 31;
    const int n = blockIdx.x * 4 + warp;
    const unsigned FULL = 0xffffffffu;
    const bool val = lane < Tt;
    const int lanec = val ? lane : (Tt - 1);

    const int* yr = y + (size_t)n * Bn;
    const float* em = g_probs + (size_t)n * Bn * Tt;

    // ---- numerator ----
    float num = 0.f;
    for (int l = lane; l < Bn; l += 32) {
        int tg = clamp_tag(yr[l]);
        num += em[l * Tt + tg];
        if (l + 1 < Bn) num += trans[tg * Tt + clamp_tag(yr[l + 1])];
    }
    #pragma unroll
    for (int o = 16; o; o >>= 1) num += __shfl_xor_sync(FULL, num, o);

    // ---- forward algorithm ----
    float et[Tt];
    #pragma unroll
    for (int i = 0; i < Tt; i++)
        et[i] = val ? __expf(trans[i * Tt + lanec]) : 0.f;

    float alpha = val ? (start_t[lanec] + em[lanec]) : 0.f;
    float e1 = em[1 * Tt + lanec];
    float e2 = em[2 * Tt + lanec];

    for (int l = 1; l < Bn; l++) {
        float ecur = e1;
        e1 = e2;
        e2 = (l + 2 < Bn) ? em[(size_t)(l + 2) * Tt + lanec] : 0.f;
        float m = __shfl_sync(FULL, alpha, 0);
        float pv = val ? __expf(alpha - m) : 0.f;
        pbuf[warp][lane] = pv;
        __syncwarp();
        float s0 = 0.f, s1 = 0.f;
        #pragma unroll
        for (int i = 0; i < 10; i++) s0 = fmaf(pbuf[warp][i], et[i], s0);
        #pragma unroll
        for (int i = 10; i < Tt; i++) s1 = fmaf(pbuf[warp][i], et[i], s1);
        alpha = m + __logf(s0 + s1) + ecur;
        __syncwarp();
    }

    float v = val ? (alpha + end_t[lanec]) : -FLT_MAX;
    float m = v;
    #pragma unroll
    for (int o = 16; o; o >>= 1) m = fmaxf(m, __shfl_xor_sync(FULL, m, o));
    float e = val ? __expf(v - m) : 0.f;
    float ss = e;
    #pragma unroll
    for (int o = 16; o; o >>= 1) ss += __shfl_xor_sync(FULL, ss, o);
    if (lane == 0) {
        float den = m + __logf(ss);
        g_nd[n] = (num + start_t[clamp_tag(yr[0])] + end_t[clamp_tag(yr[Bn - 1])]) - den;
    }
}

// ============================================================================
// Stage 5: deterministic final reduction -> scalar.
// ============================================================================
__global__ void final_reduce(float* __restrict__ out)
{
    __shared__ float sh[512];
    int tid = threadIdx.x;
    sh[tid] = g_nd[tid];
    __syncthreads();
    for (int st = 256; st; st >>= 1) {
        if (tid < st) sh[tid] += sh[tid + st];
        __syncthreads();
    }
    if (tid == 0) out[0] = sh[0];
}

// ---------------------------------------------------------------------------
extern "C" void kernel_launch(void* const* d_in, const int* in_sizes, int n_in,
                              void* d_out, int out_size)
{
    (void)in_sizes; (void)n_in; (void)out_size;
    const float* x      = (const float*)d_in[0];
    const int*   y      = (const int*)d_in[1];    // int32 (JAX x64 disabled)
    const float* Wihf   = (const float*)d_in[2];
    const float* Whhf   = (const float*)d_in[3];
    const float* bihf   = (const float*)d_in[4];
    const float* bhhf   = (const float*)d_in[5];
    const float* Wihb   = (const float*)d_in[6];
    const float* Whhb   = (const float*)d_in[7];
    const float* bihb   = (const float*)d_in[8];
    const float* bhhb   = (const float*)d_in[9];
    const float* Wtag   = (const float*)d_in[10];
    const float* btag   = (const float*)d_in[11];
    const float* startt = (const float*)d_in[12];
    const float* endt   = (const float*)d_in[13];
    const float* trans  = (const float*)d_in[14];

    cudaFuncSetAttribute(proj_mma, cudaFuncAttributeMaxDynamicSharedMemorySize, PROJ_SMEM);

    proj_mma   <<<148, 256, PROJ_SMEM>>>(x, Wihf, Wihb, bihf, bhhf, bihb, bhhb);
    rnn_scan   <<<512, 128>>>(Whhf, Whhb);
    tag_softmax<<<1024, 256>>>(Wtag, btag);
    crf_kernel <<<128, 128>>>(y, trans, startt, endt);
    final_reduce<<<1, 512>>>((float*)d_out);
}

// round 16
// speedup vs baseline: 1.1621x; 1.1621x over previous
#include <cuda_runtime.h>
#include <cuda_bf16.h>
#include <math.h>
#include <float.h>
#include <stdint.h>

#define S   512
#define Bn  256
#define DIN 202
#define Hh  100
#define Tt  19
#define SB  (S*Bn)

// ---------------- scratch (device globals; no runtime allocation) ----------
__device__ float g_xp[SB * 200];     // input projections (biases included)
__device__ float g_h [SB * 200];     // concatenated hidden states
__device__ float g_probs[SB * Tt];   // softmax emissions
__device__ float g_nd[S];            // per-sequence (num - den)

// ---- profiling-shift dummies: ncu captures "my launch #4"; these 3 no-ops
// shift the captured launch to proj_mma so next round has GEMM-side data. ----
__global__ void prof_shift_a() {}
__global__ void prof_shift_b() {}
__global__ void prof_shift_c() {}

// ============================================================================
// Stage 1 (exact R8 version, part of the 926us run): persistent bf16 GEMM via
// mma.sync.m16n8k16. D[131072,200] = x @ W^T, K padded 202->208 (13x16),
// N tiled 25 x 8. W in smem bf16 once per block; A chunks (128x16) double-
// buffered with XOR-swizzled rows.
// ============================================================================
#define KCHUNKS 13
#define NTILES  25
#define MTILES  (SB / 128)           // 1024
#define B_STRIDE 210                 // bf16 per W row (208 + 2 pad)
#define SM_BIAS  0
#define SM_B     1024
#define B_BYTES  (208 * B_STRIDE * 2)         // 87360
#define SM_A     (SM_B + B_BYTES)             // 88384
#define A_BYTES  (2 * 128 * 16 * 2)           // 8192
#define PROJ_SMEM (SM_A + A_BYTES)            // 96576

__global__ __launch_bounds__(256, 1) void proj_mma(
    const float* __restrict__ x,
    const float* __restrict__ Wf, const float* __restrict__ Wb,
    const float* __restrict__ bif, const float* __restrict__ bhf,
    const float* __restrict__ bib, const float* __restrict__ bhb)
{
    extern __shared__ __align__(16) char smem[];
    float*         bias_s = (float*)(smem + SM_BIAS);
    __nv_bfloat16* Bs     = (__nv_bfloat16*)(smem + SM_B);
    __nv_bfloat16* As     = (__nv_bfloat16*)(smem + SM_A);

    const int tid  = threadIdx.x;
    const int w    = tid >> 5, lane = tid & 31;
    const int g    = lane >> 2, tig = lane & 3;
    const int arow = tid & 127, ahalf = tid >> 7;

    for (int i = tid; i < (B_BYTES + A_BYTES) / 16; i += 256)
        ((uint4*)(smem + SM_B))[i] = make_uint4(0, 0, 0, 0);
    if (tid < 100) {
        bias_s[tid]       = bif[tid] + bhf[tid];
        bias_s[100 + tid] = bib[tid] + bhb[tid];
    }
    __syncthreads();

    // ---- W -> smem bf16, once ----
    for (int idx = tid; idx < 200 * 101; idx += 256) {
        const int n = idx / 101, j = idx % 101;
        const float2 v = ((const float2*)((n < 100) ? (Wf + (size_t)n * DIN)
                                                    : (Wb + (size_t)(n - 100) * DIN)))[j];
        __nv_bfloat162 h2 = __floats2bfloat162_rn(v.x, v.y);
        *(uint32_t*)&Bs[n * B_STRIDE + 2 * j] = *(uint32_t*)&h2;
    }
    __syncthreads();

    for (int tile = blockIdx.x; tile < MTILES; tile += gridDim.x) {
        const float2* xrow2 = (const float2*)(x + (size_t)(tile * 128 + arow) * DIN);

        {
            uint32_t* b0w = (uint32_t*)As;
            #pragma unroll
            for (int i = 0; i < 4; i++) {
                const int p = ahalf * 4 + i;
                float2 v = xrow2[p];
                __nv_bfloat162 h2 = __floats2bfloat162_rn(v.x, v.y);
                b0w[arow * 8 + ((ahalf * 4 + i) ^ (arow & 7))] = *(uint32_t*)&h2;
            }
        }
        __syncthreads();

        float c[NTILES][4];
        #pragma unroll
        for (int j = 0; j < NTILES; j++)
            #pragma unroll
            for (int q = 0; q < 4; q++) c[j][q] = 0.f;

        float2 r[4];
        #pragma unroll 1
        for (int kc = 0; kc < KCHUNKS; kc++) {
            if (kc < KCHUNKS - 1) {
                const int base = (kc + 1) * 8 + ahalf * 4;
                #pragma unroll
                for (int i = 0; i < 4; i++) {
                    const int p = base + i;
                    r[i] = (p < 101) ? xrow2[p] : make_float2(0.f, 0.f);
                }
            }
            const uint32_t* curw = (const uint32_t*)(As + (kc & 1) * 2048);
            const int r0 = w * 16 + g, r1 = r0 + 8;
            const uint32_t a0 = curw[r0 * 8 + (tig ^ g)];
            const uint32_t a1 = curw[r1 * 8 + (tig ^ g)];
            const uint32_t a2 = curw[r0 * 8 + ((tig + 4) ^ g)];
            const uint32_t a3 = curw[r1 * 8 + ((tig + 4) ^ g)];
            const int kb = kc * 16 + tig * 2;
            #pragma unroll
            for (int j = 0; j < NTILES; j++) {
                const __nv_bfloat16* bp = Bs + (8 * j + g) * B_STRIDE + kb;
                const uint32_t b0 = *(const uint32_t*)bp;
                const uint32_t b1 = *(const uint32_t*)(bp + 8);
                asm volatile(
                    "mma.sync.aligned.m16n8k16.row.col.f32.bf16.bf16.f32 "
                    "{%0,%1,%2,%3}, {%4,%5,%6,%7}, {%8,%9}, {%0,%1,%2,%3};"
                    : "+f"(c[j][0]), "+f"(c[j][1]), "+f"(c[j][2]), "+f"(c[j][3])
                    : "r"(a0), "r"(a1), "r"(a2), "r"(a3), "r"(b0), "r"(b1));
            }
            if (kc < KCHUNKS - 1) {
                uint32_t* nxtw = (uint32_t*)(As + ((kc + 1) & 1) * 2048);
                #pragma unroll
                for (int i = 0; i < 4; i++) {
                    __nv_bfloat162 h2 = __floats2bfloat162_rn(r[i].x, r[i].y);
                    nxtw[arow * 8 + ((ahalf * 4 + i) ^ (arow & 7))] = *(uint32_t*)&h2;
                }
                __syncthreads();
            }
        }

        const int m0 = tile * 128 + w * 16;
        #pragma unroll
        for (int j = 0; j < NTILES; j++) {
            const int col = 8 * j + tig * 2;
            const float bx = bias_s[col], by = bias_s[col + 1];
            float2 v0 = make_float2(c[j][0] + bx, c[j][1] + by);
            float2 v1 = make_float2(c[j][2] + bx, c[j][3] + by);
            *(float2*)&g_xp[(size_t)(m0 + g)     * 200 + col] = v0;
            *(float2*)&g_xp[(size_t)(m0 + g + 8) * 200 + col] = v1;
        }
        __syncthreads();
    }
}

// ============================================================================
// Stage 2 (R8 scalar version + __launch_bounds__(128,4)): the ONLY change this
// round. ~115 regs fits the 128-reg cap without spills -> 4 blocks/SM -> all
// 512 blocks in ONE wave (was 444 + 68 straggler wave at 3 blocks/SM).
// ============================================================================
__global__ __launch_bounds__(128, 4) void rnn_scan(
    const float* __restrict__ Whf, const float* __restrict__ Whb)
{
    const int dir = (blockIdx.x >= Bn) ? 1 : 0;
    const int b   = dir ? (blockIdx.x - Bn) : blockIdx.x;
    const int tid = threadIdx.x;
    const float* Whh = dir ? Whb : Whf;
    const bool act = tid < 100;

    __shared__ __align__(16) float hs[2][100];

    float w[100];
    if (act) {
        #pragma unroll
        for (int j = 0; j < 100; j++) w[j] = Whh[tid * 100 + j];
        hs[0][tid] = 0.f;
    }

    const size_t base = (size_t)b * 200 + (size_t)dir * 100 + tid;
    float pf[4];
    #pragma unroll
    for (int i = 0; i < 4; i++) {
        int t = dir ? (S - 1 - i) : i;
        pf[i] = act ? g_xp[(size_t)t * (Bn * 200) + base] : 0.f;
    }
    __syncthreads();

    int p = 0;
    for (int step = 0; step < S; step++) {
        const int t = dir ? (S - 1 - step) : step;
        float acc = pf[step & 3];
        if (step + 4 < S && act) {
            int t4 = dir ? (S - 1 - (step + 4)) : (step + 4);
            pf[step & 3] = g_xp[(size_t)t4 * (Bn * 200) + base];
        }
        if (act) {
            float s0 = acc, s1 = 0.f, s2 = 0.f, s3 = 0.f;
            #pragma unroll
            for (int jj = 0; jj < 25; jj++) {
                float4 h4 = *(const float4*)&hs[p][jj * 4];
                s0 = fmaf(h4.x, w[jj * 4 + 0], s0);
                s1 = fmaf(h4.y, w[jj * 4 + 1], s1);
                s2 = fmaf(h4.z, w[jj * 4 + 2], s2);
                s3 = fmaf(h4.w, w[jj * 4 + 3], s3);
            }
            float s = (s0 + s1) + (s2 + s3);
            float e = __expf(2.f * s);                    // tanh = 1 - 2/(e^{2s}+1)
            float nh = 1.f - __fdividef(2.f, e + 1.f);
            hs[p ^ 1][tid] = nh;
            g_h[(size_t)t * (Bn * 200) + base] = nh;
        }
        __syncthreads();
        p ^= 1;
    }
}

// ============================================================================
// Stage 3 (exact R8 version): logits + softmax, warp per row.
// ============================================================================
__global__ __launch_bounds__(128) void tag_softmax(
    const float* __restrict__ Wtag, const float* __restrict__ btag)
{
    __shared__ __align__(16) float hrow[4][200];
    __shared__ __align__(16) float Wt[200 * Tt];   // [h][t]
    __shared__ float bt[Tt];
    const int tid = threadIdx.x;

    for (int idx = tid; idx < 200 * Tt; idx += 128) {
        int h = idx / Tt, t = idx % Tt;
        Wt[idx] = Wtag[t * 200 + h];
    }
    if (tid < Tt) bt[tid] = btag[tid];
    __syncthreads();

    const int warp = tid >> 5, lane = tid & 31;
    const unsigned FULL = 0xffffffffu;
    for (int row = blockIdx.x * 4 + warp; row < SB; row += gridDim.x * 4) {
        const float* hr = g_h + (size_t)row * 200;
        for (int i = lane; i < 200; i += 32) hrow[warp][i] = hr[i];
        __syncwarp();
        float acc = 0.f;
        if (lane < Tt) {
            float a0 = 0.f, a1 = 0.f, a2 = 0.f, a3 = 0.f;
            #pragma unroll
            for (int h4 = 0; h4 < 50; h4++) {
                float4 hv = *(const float4*)&hrow[warp][h4 * 4];
                a0 = fmaf(hv.x, Wt[(h4 * 4 + 0) * Tt + lane], a0);
                a1 = fmaf(hv.y, Wt[(h4 * 4 + 1) * Tt + lane], a1);
                a2 = fmaf(hv.z, Wt[(h4 * 4 + 2) * Tt + lane], a2);
                a3 = fmaf(hv.w, Wt[(h4 * 4 + 3) * Tt + lane], a3);
            }
            acc = bt[lane] + ((a0 + a1) + (a2 + a3));
        }
        float v = (lane < Tt) ? acc : -FLT_MAX;
        float m = v;
        #pragma unroll
        for (int o = 16; o; o >>= 1) m = fmaxf(m, __shfl_xor_sync(FULL, m, o));
        float e = (lane < Tt) ? __expf(acc - m) : 0.f;
        float ssum = e;
        #pragma unroll
        for (int o = 16; o; o >>= 1) ssum += __shfl_xor_sync(FULL, ssum, o);
        if (lane < Tt) g_probs[(size_t)row * Tt + lane] = e / ssum;
        __syncwarp();
    }
}

// ============================================================================
// Stage 4 (exact R8 version, measured 48.8-49.6us): fused CRF num + forward.
// ============================================================================
__device__ __forceinline__ int clamp_tag(int t) {
    return t < 0 ? 0 : (t >= Tt ? Tt - 1 : t);
}

__global__ __launch_bounds__(128) void crf_kernel(
    const int* __restrict__ y, const float* __restrict__ trans,
    const float* __restrict__ start_t, const float* __restrict__ end_t)
{
    __shared__ __align__(16) float pbuf[4][32];
    const int tid = threadIdx.x, warp = tid >> 5, lane = tid & 31;
    const int n = blockIdx.x * 4 + warp;
    const unsigned FULL = 0xffffffffu;
    const bool val = lane < Tt;
    const int lanec = val ? lane : (Tt - 1);

    const int* yr = y + (size_t)n * Bn;
    const float* em = g_probs + (size_t)n * Bn * Tt;

    float num = 0.f;
    for (int l = lane; l < Bn; l += 32) {
        int tg = clamp_tag(yr[l]);
        num += em[l * Tt + tg];
        if (l + 1 < Bn) num += trans[tg * Tt + clamp_tag(yr[l + 1])];
    }
    #pragma unroll
    for (int o = 16; o; o >>= 1) num += __shfl_xor_sync(FULL, num, o);

    float et[Tt];
    #pragma unroll
    for (int i = 0; i < Tt; i++)
        et[i] = val ? __expf(trans[i * Tt + lanec]) : 0.f;

    float alpha = val ? (start_t[lanec] + em[lanec]) : 0.f;
    float e1 = em[1 * Tt + lanec];
    float e2 = em[2 * Tt + lanec];

    for (int l = 1; l < Bn; l++) {
        float ecur = e1;
        e1 = e2;
        e2 = (l + 2 < Bn) ? em[(size_t)(l + 2) * Tt + lanec] : 0.f;
        float m = __shfl_sync(FULL, alpha, 0);
        float pv = val ? __expf(alpha - m) : 0.f;
        pbuf[warp][lane] = pv;
        __syncwarp();
        float s0 = 0.f, s1 = 0.f;
        #pragma unroll
        for (int i = 0; i < 10; i++) s0 = fmaf(pbuf[warp][i], et[i], s0);
        #pragma unroll
        for (int i = 10; i < Tt; i++) s1 = fmaf(pbuf[warp][i], et[i], s1);
        alpha = m + __logf(s0 + s1) + ecur;
        __syncwarp();
    }

    float v = val ? (alpha + end_t[lanec]) : -FLT_MAX;
    float m = v;
    #pragma unroll
    for (int o = 16; o; o >>= 1) m = fmaxf(m, __shfl_xor_sync(FULL, m, o));
    float e = val ? __expf(v - m) : 0.f;
    float ss = e;
    #pragma unroll
    for (int o = 16; o; o >>= 1) ss += __shfl_xor_sync(FULL, ss, o);
    if (lane == 0) {
        float den = m + __logf(ss);
        g_nd[n] = (num + start_t[clamp_tag(yr[0])] + end_t[clamp_tag(yr[Bn - 1])]) - den;
    }
}

// ============================================================================
// Stage 5: deterministic final reduction -> scalar.
// ============================================================================
__global__ void final_reduce(float* __restrict__ out)
{
    __shared__ float sh[512];
    int tid = threadIdx.x;
    sh[tid] = g_nd[tid];
    __syncthreads();
    for (int st = 256; st; st >>= 1) {
        if (tid < st) sh[tid] += sh[tid + st];
        __syncthreads();
    }
    if (tid == 0) out[0] = sh[0];
}

// ---------------------------------------------------------------------------
extern "C" void kernel_launch(void* const* d_in, const int* in_sizes, int n_in,
                              void* d_out, int out_size)
{
    (void)in_sizes; (void)n_in; (void)out_size;
    const float* x      = (const float*)d_in[0];
    const int*   y      = (const int*)d_in[1];    // int32 (JAX x64 disabled)
    const float* Wihf   = (const float*)d_in[2];
    const float* Whhf   = (const float*)d_in[3];
    const float* bihf   = (const float*)d_in[4];
    const float* bhhf   = (const float*)d_in[5];
    const float* Wihb   = (const float*)d_in[6];
    const float* Whhb   = (const float*)d_in[7];
    const float* bihb   = (const float*)d_in[8];
    const float* bhhb   = (const float*)d_in[9];
    const float* Wtag   = (const float*)d_in[10];
    const float* btag   = (const float*)d_in[11];
    const float* startt = (const float*)d_in[12];
    const float* endt   = (const float*)d_in[13];
    const float* trans  = (const float*)d_in[14];

    cudaFuncSetAttribute(proj_mma, cudaFuncAttributeMaxDynamicSharedMemorySize, PROJ_SMEM);

    // ncu captures "my launch #4" -> with 3 dummies that is proj_mma.
    prof_shift_a<<<1, 32>>>();
    prof_shift_b<<<1, 32>>>();
    prof_shift_c<<<1, 32>>>();
    proj_mma   <<<148, 256, PROJ_SMEM>>>(x, Wihf, Wihb, bihf, bhhf, bihb, bhhb);
    rnn_scan   <<<512, 128>>>(Whhf, Whhb);
    tag_softmax<<<2048, 128>>>(Wtag, btag);
    crf_kernel <<<128, 128>>>(y, trans, startt, endt);
    final_reduce<<<1, 512>>>((float*)d_out);
}